// round 14
// baseline (speedup 1.0000x reference)
#include <cuda_runtime.h>
#include <cuda_fp16.h>
#include <cstdint>

#define NN   100000
#define EE   1600000
#define HH   128
#define GG   256
#define CC   25
#define LL   3
#define FIN  10
#define BN_EPS 1e-5f
#define CAP  96          // max degree bucket capacity (Poisson(16) tail @96 ~ 0)

// ---------------- scratch (device globals; no allocation) ----------------
__device__ __half   g_h[(size_t)NN * HH];
__device__ __half   g_hw[(size_t)NN * HH];      // dinv-scaled: hw_s[x] = dinv[x]*(h@W)[x]
__device__ uint32_t g_Wf[LL * 8192];            // W packed as mma B-fragments, all layers
__device__ int      g_deg[NN];
__device__ int      g_adj[(size_t)NN * CAP];    // bucketed adjacency
__device__ float    g_bnA[LL * HH];
__device__ float    g_bnB[LL * HH];
__device__ float    g_psum[GG * HH];
__device__ float    g_pmax[GG * HH];
__device__ int      g_cnt[GG];

// ---------------- init: zero degree + pooling buffers ----------------
__global__ void k_init() {
    int i = blockIdx.x * blockDim.x + threadIdx.x;
    if (i < NN) g_deg[i] = 0;
    if (i < GG * HH) { g_psum[i] = 0.0f; g_pmax[i] = 0.0f; }
    if (i < GG) g_cnt[i] = 0;
}

// ---------------- single-pass bucketed adjacency build (4 edges/thread) ----------------
__global__ void k_fill(const int4* __restrict__ rows4, const int4* __restrict__ cols4) {
    int t = blockIdx.x * blockDim.x + threadIdx.x;
    if (t >= EE / 4) return;
    int4 r = rows4[t];
    int4 c = cols4[t];
    int p0 = atomicAdd(&g_deg[r.x], 1); g_adj[(size_t)r.x * CAP + p0] = c.x;
    int p1 = atomicAdd(&g_deg[r.y], 1); g_adj[(size_t)r.y * CAP + p1] = c.y;
    int p2 = atomicAdd(&g_deg[r.z], 1); g_adj[(size_t)r.z * CAP + p2] = c.z;
    int p3 = atomicAdd(&g_deg[r.w], 1); g_adj[(size_t)r.w * CAP + p3] = c.w;
}

// ---------------- prep: all layers' BN terms + W mma B-fragments ----------------
// frag idx = kc*1024 + nt*64 + lane*2 + r ; k = kc*16+(lane&3)*2+r*8, n = nt*8+(lane>>2)
__global__ void k_prep(const float* __restrict__ Wc,
                       const float* __restrict__ bc, const float* __restrict__ gamma,
                       const float* __restrict__ beta, const float* __restrict__ mean,
                       const float* __restrict__ var) {
    int l = blockIdx.x >> 5;                    // layer
    int bi = blockIdx.x & 31;
    int i = bi * 256 + threadIdx.x;             // 0..8191 within layer
    if (bi == 0 && threadIdx.x < HH) {
        int t = threadIdx.x;
        float A = gamma[l * HH + t] * rsqrtf(var[l * HH + t] + BN_EPS);
        g_bnA[l * HH + t] = A;
        g_bnB[l * HH + t] = (bc[l * HH + t] - mean[l * HH + t]) * A + beta[l * HH + t];
    }
    const float* W = Wc + (size_t)l * HH * HH;
    int r    = i & 1;
    int lane = (i >> 1) & 31;
    int nt   = (i >> 6) & 15;
    int kc   = i >> 10;
    int n = nt * 8 + (lane >> 2);
    int k = kc * 16 + (lane & 3) * 2 + r * 8;
    __half2 p = __floats2half2_rn(W[k * HH + n], W[(k + 1) * HH + n]);
    g_Wf[l * 8192 + i] = *(uint32_t*)&p;
}

// ---------------- projection: h = relu(x @ Wp + bp) -> fp16 ----------------
__global__ void k_proj(const float* __restrict__ x, const float* __restrict__ Wp,
                       const float* __restrict__ bp) {
    __shared__ float sW[FIN * HH];
    __shared__ float sb[HH];
    int t = threadIdx.x;  // 128
    for (int i = t; i < FIN * HH; i += HH) sW[i] = Wp[i];
    sb[t] = bp[t];
    __syncthreads();
    int n0 = blockIdx.x * 64;
    for (int i = 0; i < 64; i++) {
        int n = n0 + i;
        if (n >= NN) break;
        float acc = sb[t];
#pragma unroll
        for (int k = 0; k < FIN; k++)
            acc = fmaf(x[(size_t)n * FIN + k], sW[k * HH + t], acc);
        g_h[(size_t)n * HH + t] = __float2half(fmaxf(acc, 0.0f));
    }
}

// ---------------- HMMA GEMM: g_hw = dinv * (g_h @ W) ----------------
// block = 256 thr (8 warps), 128 rows/block; warp = 16 rows x 128 cols.
// B fragments read directly from L2-resident g_Wf (no smem staging) -> 32KB smem,
// up to 7 CTAs/SM instead of 3.
__global__ void __launch_bounds__(256) k_gemm_hmma(int layer) {
    extern __shared__ char smem[];
    __half* hs = (__half*)smem;                  // 128 x 256B, swizzled

    int tid = threadIdx.x;
    int row0 = blockIdx.x * 128;

    for (int i = tid; i < 2048; i += 256) {
        int row = i >> 4, c = i & 15;
        int gr = row0 + row;
        uint4 v = make_uint4(0u, 0u, 0u, 0u);
        if (gr < NN) v = ((const uint4*)(g_h + (size_t)gr * HH))[c];
        uint32_t off = (uint32_t)(row * 256 + c * 16);
        off ^= (off >> 4) & 0x70;
        *(uint4*)((char*)hs + off) = v;
    }
    __syncthreads();

    int warp = tid >> 5, lane = tid & 31;
    float acc[16][4];
#pragma unroll
    for (int nt = 0; nt < 16; nt++)
#pragma unroll
        for (int j = 0; j < 4; j++) acc[nt][j] = 0.0f;

    uint32_t hs_s = (uint32_t)__cvta_generic_to_shared(hs);
    int arow = warp * 16 + (lane & 15);
    int koff = (lane >> 4) * 16;
    const uint2* wfrag = (const uint2*)(g_Wf + layer * 8192);

#pragma unroll
    for (int kc = 0; kc < 8; kc++) {
        uint32_t off = (uint32_t)(arow * 256 + kc * 32 + koff);
        off ^= (off >> 4) & 0x70;
        uint32_t a0, a1, a2, a3;
        asm volatile("ldmatrix.sync.aligned.m8n8.x4.shared.b16 {%0,%1,%2,%3}, [%4];"
                     : "=r"(a0), "=r"(a1), "=r"(a2), "=r"(a3)
                     : "r"(hs_s + off));
        const uint2* wb = wfrag + (size_t)kc * 512 + lane;
#pragma unroll
        for (int nt = 0; nt < 16; nt++) {
            uint2 b = __ldg(wb + nt * 32);
            asm volatile(
                "mma.sync.aligned.m16n8k16.row.col.f32.f16.f16.f32 "
                "{%0,%1,%2,%3}, {%4,%5,%6,%7}, {%8,%9}, {%0,%1,%2,%3};"
                : "+f"(acc[nt][0]), "+f"(acc[nt][1]), "+f"(acc[nt][2]), "+f"(acc[nt][3])
                : "r"(a0), "r"(a1), "r"(a2), "r"(a3), "r"(b.x), "r"(b.y));
        }
    }

    int r0 = row0 + warp * 16 + (lane >> 2);
    int r1 = r0 + 8;
    int cb = (lane & 3) * 2;
    float s0 = (r0 < NN) ? rsqrtf(1.0f + (float)g_deg[r0]) : 0.0f;
    float s1 = (r1 < NN) ? rsqrtf(1.0f + (float)g_deg[r1]) : 0.0f;
#pragma unroll
    for (int nt = 0; nt < 16; nt++) {
        int col = nt * 8 + cb;
        if (r0 < NN) {
            __half2 p = __floats2half2_rn(acc[nt][0] * s0, acc[nt][1] * s0);
            *(uint32_t*)(g_hw + (size_t)r0 * HH + col) = *(uint32_t*)&p;
        }
        if (r1 < NN) {
            __half2 p = __floats2half2_rn(acc[nt][2] * s1, acc[nt][3] * s1);
            *(uint32_t*)(g_hw + (size_t)r1 * HH + col) = *(uint32_t*)&p;
        }
    }
}

// ---------------- fused gather (dinv-scaled fp16 rows) + BN + ReLU -> fp16 h ----------------
__device__ __forceinline__ void add_half4(float4& acc, uint2 u) {
    __half2 p0 = *(__half2*)&u.x;
    __half2 p1 = *(__half2*)&u.y;
    float2 f0 = __half22float2(p0);
    float2 f1 = __half22float2(p1);
    acc.x += f0.x; acc.y += f0.y;
    acc.z += f1.x; acc.w += f1.y;
}

__global__ void k_gather_bn(int layer) {
    int node = blockIdx.x * 4 + (threadIdx.x >> 5);
    if (node >= NN) return;
    int lane = threadIdx.x & 31;

    // self term: agg = dinv[node] * (hw_s[node] + sum hw_s[col])
    float4 acc = make_float4(0.f, 0.f, 0.f, 0.f);
    add_half4(acc, ((const uint2*)(g_hw + (size_t)node * HH))[lane]);

    int deg = g_deg[node];
    const int* adj = g_adj + (size_t)node * CAP;
    for (int base = 0; base < deg; base += 32) {
        int n = deg - base;
        if (n > 32) n = 32;
        int cidx = (lane < n) ? adj[base + lane] : 0;
        int j = 0;
        for (; j + 3 < n; j += 4) {
            int c0 = __shfl_sync(0xffffffffu, cidx, j);
            int c1 = __shfl_sync(0xffffffffu, cidx, j + 1);
            int c2 = __shfl_sync(0xffffffffu, cidx, j + 2);
            int c3 = __shfl_sync(0xffffffffu, cidx, j + 3);
            uint2 u0 = ((const uint2*)(g_hw + (size_t)c0 * HH))[lane];
            uint2 u1 = ((const uint2*)(g_hw + (size_t)c1 * HH))[lane];
            uint2 u2 = ((const uint2*)(g_hw + (size_t)c2 * HH))[lane];
            uint2 u3 = ((const uint2*)(g_hw + (size_t)c3 * HH))[lane];
            add_half4(acc, u0);
            add_half4(acc, u1);
            add_half4(acc, u2);
            add_half4(acc, u3);
        }
        for (; j < n; j++) {
            int c = __shfl_sync(0xffffffffu, cidx, j);
            add_half4(acc, ((const uint2*)(g_hw + (size_t)c * HH))[lane]);
        }
    }

    float dr = rsqrtf(1.0f + (float)deg);
    float4 A = ((const float4*)(g_bnA + layer * HH))[lane];
    float4 B = ((const float4*)(g_bnB + layer * HH))[lane];
    __half2 p0 = __floats2half2_rn(fmaxf(fmaf(acc.x * dr, A.x, B.x), 0.f),
                                   fmaxf(fmaf(acc.y * dr, A.y, B.y), 0.f));
    __half2 p1 = __floats2half2_rn(fmaxf(fmaf(acc.z * dr, A.z, B.z), 0.f),
                                   fmaxf(fmaf(acc.w * dr, A.w, B.w), 0.f));
    uint2 o = make_uint2(*(uint32_t*)&p0, *(uint32_t*)&p1);
    ((uint2*)(g_h + (size_t)node * HH))[lane] = o;
}

// ---------------- pooling (batch sorted: register segments, flush on boundary) ----------------
__global__ void k_pool(const int* __restrict__ batch) {
    int f = threadIdx.x;
    int n0 = blockIdx.x * 32;
    int curg = batch[n0];
    float s = 0.f, m = 0.f;
    int c = 0;
    for (int i = 0; i < 32; i++) {
        int n = n0 + i;
        if (n >= NN) break;
        int g = batch[n];
        if (g != curg) {
            atomicAdd(&g_psum[curg * HH + f], s);
            atomicMax((int*)&g_pmax[curg * HH + f], __float_as_int(m));
            if (f == 0) atomicAdd(&g_cnt[curg], c);
            s = 0.f; m = 0.f; c = 0; curg = g;
        }
        float v = __half2float(g_h[(size_t)n * HH + f]);
        s += v;
        m = fmaxf(m, v);
        c++;
    }
    atomicAdd(&g_psum[curg * HH + f], s);
    atomicMax((int*)&g_pmax[curg * HH + f], __float_as_int(m));
    if (f == 0) atomicAdd(&g_cnt[curg], c);
}

// ---------------- final MLP ----------------
__global__ void k_mlp(const float* __restrict__ W1, const float* __restrict__ b1,
                      const float* __restrict__ W2, const float* __restrict__ b2,
                      float* __restrict__ out) {
    __shared__ float gv[2 * HH];
    __shared__ float hid[HH];
    int g = blockIdx.x, t = threadIdx.x;  // 128
    float cntf = fmaxf((float)g_cnt[g], 1.0f);
    gv[t] = g_psum[g * HH + t] / cntf;
    gv[HH + t] = g_pmax[g * HH + t];
    __syncthreads();
    float acc = b1[t];
#pragma unroll 8
    for (int k = 0; k < 2 * HH; k++)
        acc = fmaf(gv[k], W1[k * HH + t], acc);
    hid[t] = fmaxf(acc, 0.0f);
    __syncthreads();
    if (t < CC) {
        float o = b2[t];
#pragma unroll 8
        for (int c = 0; c < HH; c++)
            o = fmaf(hid[c], W2[c * CC + t], o);
        out[g * CC + t] = o;
    }
}

// ---------------- persistent side streams/events (created once; no device mem) ----------------
static cudaStream_t make_stream() {
    cudaStream_t s;
    cudaStreamCreateWithFlags(&s, cudaStreamNonBlocking);
    return s;
}
static cudaEvent_t make_event() {
    cudaEvent_t e;
    cudaEventCreateWithFlags(&e, cudaEventDisableTiming);
    return e;
}

// ---------------- launch ----------------
extern "C" void kernel_launch(void* const* d_in, const int* in_sizes, int n_in,
                              void* d_out, int out_size) {
    const float* x     = (const float*)d_in[0];
    const int*   ei    = (const int*)d_in[1];
    const int*   batch = (const int*)d_in[2];
    const float* Wp    = (const float*)d_in[3];
    const float* bp    = (const float*)d_in[4];
    const float* Wc    = (const float*)d_in[5];
    const float* bc    = (const float*)d_in[6];
    const float* bn_g  = (const float*)d_in[7];
    const float* bn_b  = (const float*)d_in[8];
    const float* bn_m  = (const float*)d_in[9];
    const float* bn_v  = (const float*)d_in[10];
    const float* W1    = (const float*)d_in[11];
    const float* b1    = (const float*)d_in[12];
    const float* W2    = (const float*)d_in[13];
    const float* b2    = (const float*)d_in[14];
    float* out = (float*)d_out;

    const int4* rows4 = (const int4*)ei;
    const int4* cols4 = (const int4*)(ei + EE);

    static cudaStream_t s1 = make_stream();
    static cudaEvent_t ev_fork = make_event();
    static cudaEvent_t ev_j1 = make_event();

    const int gemm_smem = 32768;

    // fork: prep + proj (side stream) run concurrently with adjacency build (stream 0)
    cudaEventRecord(ev_fork, 0);
    cudaStreamWaitEvent(s1, ev_fork, 0);

    k_prep<<<LL * 32, 256, 0, s1>>>(Wc, bc, bn_g, bn_b, bn_m, bn_v);
    k_proj<<<(NN + 63) / 64, 128, 0, s1>>>(x, Wp, bp);

    k_init<<<(NN + 255) / 256, 256>>>();
    k_fill<<<(EE / 4 + 255) / 256, 256>>>(rows4, cols4);

    // join
    cudaEventRecord(ev_j1, s1);
    cudaStreamWaitEvent(0, ev_j1, 0);

    for (int l = 0; l < LL; l++) {
        k_gemm_hmma<<<(NN + 127) / 128, 256, gemm_smem>>>(l);
        k_gather_bn<<<(NN + 3) / 4, 128>>>(l);
    }

    k_pool<<<NN / 32, 128>>>(batch);
    k_mlp<<<GG, 128>>>(W1, b1, W2, b2, out);
}

// round 15
// speedup vs baseline: 1.2804x; 1.2804x over previous
#include <cuda_runtime.h>
#include <cuda_fp16.h>
#include <cstdint>

#define NN   100000
#define EE   1600000
#define HH   128
#define GG   256
#define CC   25
#define LL   3
#define FIN  10
#define BN_EPS 1e-5f
#define CAP  96          // max degree bucket capacity (Poisson(16) tail @96 ~ 0)

// ---------------- scratch (device globals; no allocation) ----------------
__device__ __half   g_h[(size_t)NN * HH];
__device__ __half   g_hw[(size_t)NN * HH];      // dinv-scaled: hw_s[x] = dinv[x]*(h@W)[x]
__device__ uint32_t g_Wf[LL * 8192];            // W packed as mma B-fragments, all layers
__device__ int      g_deg[NN];
__device__ int      g_adj[(size_t)NN * CAP];    // bucketed adjacency
__device__ float    g_bnA[LL * HH];
__device__ float    g_bnB[LL * HH];
__device__ float    g_psum[GG * HH];
__device__ float    g_pmax[GG * HH];
__device__ int      g_cnt[GG];

// ---------------- init: zero degree + pooling buffers ----------------
__global__ void k_init() {
    int i = blockIdx.x * blockDim.x + threadIdx.x;
    if (i < NN) g_deg[i] = 0;
    if (i < GG * HH) { g_psum[i] = 0.0f; g_pmax[i] = 0.0f; }
    if (i < GG) g_cnt[i] = 0;
}

// ---------------- single-pass bucketed adjacency build (4 edges/thread) ----------------
__global__ void k_fill(const int4* __restrict__ rows4, const int4* __restrict__ cols4) {
    int t = blockIdx.x * blockDim.x + threadIdx.x;
    if (t >= EE / 4) return;
    int4 r = rows4[t];
    int4 c = cols4[t];
    int p0 = atomicAdd(&g_deg[r.x], 1); g_adj[(size_t)r.x * CAP + p0] = c.x;
    int p1 = atomicAdd(&g_deg[r.y], 1); g_adj[(size_t)r.y * CAP + p1] = c.y;
    int p2 = atomicAdd(&g_deg[r.z], 1); g_adj[(size_t)r.z * CAP + p2] = c.z;
    int p3 = atomicAdd(&g_deg[r.w], 1); g_adj[(size_t)r.w * CAP + p3] = c.w;
}

// ---------------- prep: all layers' BN terms + W mma B-fragments ----------------
// frag idx = kc*1024 + nt*64 + lane*2 + r ; k = kc*16+(lane&3)*2+r*8, n = nt*8+(lane>>2)
__global__ void k_prep(const float* __restrict__ Wc,
                       const float* __restrict__ bc, const float* __restrict__ gamma,
                       const float* __restrict__ beta, const float* __restrict__ mean,
                       const float* __restrict__ var) {
    int l = blockIdx.x >> 5;                    // layer
    int bi = blockIdx.x & 31;
    int i = bi * 256 + threadIdx.x;             // 0..8191 within layer
    if (bi == 0 && threadIdx.x < HH) {
        int t = threadIdx.x;
        float A = gamma[l * HH + t] * rsqrtf(var[l * HH + t] + BN_EPS);
        g_bnA[l * HH + t] = A;
        g_bnB[l * HH + t] = (bc[l * HH + t] - mean[l * HH + t]) * A + beta[l * HH + t];
    }
    const float* W = Wc + (size_t)l * HH * HH;
    int r    = i & 1;
    int lane = (i >> 1) & 31;
    int nt   = (i >> 6) & 15;
    int kc   = i >> 10;
    int n = nt * 8 + (lane >> 2);
    int k = kc * 16 + (lane & 3) * 2 + r * 8;
    __half2 p = __floats2half2_rn(W[k * HH + n], W[(k + 1) * HH + n]);
    g_Wf[l * 8192 + i] = *(uint32_t*)&p;
}

// ---------------- projection: h = relu(x @ Wp + bp) -> fp16 ----------------
__global__ void k_proj(const float* __restrict__ x, const float* __restrict__ Wp,
                       const float* __restrict__ bp) {
    __shared__ float sW[FIN * HH];
    __shared__ float sb[HH];
    int t = threadIdx.x;  // 128
    for (int i = t; i < FIN * HH; i += HH) sW[i] = Wp[i];
    sb[t] = bp[t];
    __syncthreads();
    int n0 = blockIdx.x * 64;
    for (int i = 0; i < 64; i++) {
        int n = n0 + i;
        if (n >= NN) break;
        float acc = sb[t];
#pragma unroll
        for (int k = 0; k < FIN; k++)
            acc = fmaf(x[(size_t)n * FIN + k], sW[k * HH + t], acc);
        g_h[(size_t)n * HH + t] = __float2half(fmaxf(acc, 0.0f));
    }
}

// ---------------- HMMA GEMM: g_hw = dinv * (g_h @ W) ----------------
// block = 512 thr (16 warps), 128 rows/block; warp = 16 rows x 64 cols.
// acc = 32 regs/thread -> ~48 total regs -> 2 CTAs/SM (32 warps) instead of 24.
__global__ void __launch_bounds__(512) k_gemm_hmma(int layer) {
    extern __shared__ char smem[];
    __half*   hs = (__half*)smem;                  // 128 x 256B, swizzled
    uint32_t* wf = (uint32_t*)(smem + 32768);      // 8192 u32 B-frags

    int tid = threadIdx.x;
    int row0 = blockIdx.x * 128;

    const uint4* wsrc = (const uint4*)(g_Wf + layer * 8192);
    for (int i = tid; i < 2048; i += 512)
        ((uint4*)wf)[i] = wsrc[i];

    for (int i = tid; i < 2048; i += 512) {
        int row = i >> 4, c = i & 15;
        int gr = row0 + row;
        uint4 v = make_uint4(0u, 0u, 0u, 0u);
        if (gr < NN) v = ((const uint4*)(g_h + (size_t)gr * HH))[c];
        uint32_t off = (uint32_t)(row * 256 + c * 16);
        off ^= (off >> 4) & 0x70;
        *(uint4*)((char*)hs + off) = v;
    }
    __syncthreads();

    int warp = tid >> 5, lane = tid & 31;
    int rg = warp >> 1;          // row group 0..7 (16 rows each)
    int cg = warp & 1;           // col group 0..1 (64 cols each)

    float acc[8][4];
#pragma unroll
    for (int nt = 0; nt < 8; nt++)
#pragma unroll
        for (int j = 0; j < 4; j++) acc[nt][j] = 0.0f;

    uint32_t hs_s = (uint32_t)__cvta_generic_to_shared(hs);
    int arow = rg * 16 + (lane & 15);
    int koff = (lane >> 4) * 16;

#pragma unroll
    for (int kc = 0; kc < 8; kc++) {
        uint32_t off = (uint32_t)(arow * 256 + kc * 32 + koff);
        off ^= (off >> 4) & 0x70;
        uint32_t a0, a1, a2, a3;
        asm volatile("ldmatrix.sync.aligned.m8n8.x4.shared.b16 {%0,%1,%2,%3}, [%4];"
                     : "=r"(a0), "=r"(a1), "=r"(a2), "=r"(a3)
                     : "r"(hs_s + off));
        const uint2* wb = (const uint2*)wf + (size_t)kc * 512 + cg * 256 + lane;
#pragma unroll
        for (int nt = 0; nt < 8; nt++) {
            uint2 b = wb[nt * 32];
            asm volatile(
                "mma.sync.aligned.m16n8k16.row.col.f32.f16.f16.f32 "
                "{%0,%1,%2,%3}, {%4,%5,%6,%7}, {%8,%9}, {%0,%1,%2,%3};"
                : "+f"(acc[nt][0]), "+f"(acc[nt][1]), "+f"(acc[nt][2]), "+f"(acc[nt][3])
                : "r"(a0), "r"(a1), "r"(a2), "r"(a3), "r"(b.x), "r"(b.y));
        }
    }

    int r0 = row0 + rg * 16 + (lane >> 2);
    int r1 = r0 + 8;
    int cb = (lane & 3) * 2;
    float s0 = (r0 < NN) ? rsqrtf(1.0f + (float)g_deg[r0]) : 0.0f;
    float s1 = (r1 < NN) ? rsqrtf(1.0f + (float)g_deg[r1]) : 0.0f;
#pragma unroll
    for (int nt = 0; nt < 8; nt++) {
        int col = (cg * 8 + nt) * 8 + cb;
        if (r0 < NN) {
            __half2 p = __floats2half2_rn(acc[nt][0] * s0, acc[nt][1] * s0);
            *(uint32_t*)(g_hw + (size_t)r0 * HH + col) = *(uint32_t*)&p;
        }
        if (r1 < NN) {
            __half2 p = __floats2half2_rn(acc[nt][2] * s1, acc[nt][3] * s1);
            *(uint32_t*)(g_hw + (size_t)r1 * HH + col) = *(uint32_t*)&p;
        }
    }
}

// ---------------- fused gather (dinv-scaled fp16 rows) + BN + ReLU -> fp16 h ----------------
__device__ __forceinline__ void add_half4(float4& acc, uint2 u) {
    __half2 p0 = *(__half2*)&u.x;
    __half2 p1 = *(__half2*)&u.y;
    float2 f0 = __half22float2(p0);
    float2 f1 = __half22float2(p1);
    acc.x += f0.x; acc.y += f0.y;
    acc.z += f1.x; acc.w += f1.y;
}

__global__ void k_gather_bn(int layer) {
    int node = blockIdx.x * 4 + (threadIdx.x >> 5);
    if (node >= NN) return;
    int lane = threadIdx.x & 31;

    // self term: agg = dinv[node] * (hw_s[node] + sum hw_s[col])
    float4 acc = make_float4(0.f, 0.f, 0.f, 0.f);
    add_half4(acc, ((const uint2*)(g_hw + (size_t)node * HH))[lane]);

    int deg = g_deg[node];
    const int* adj = g_adj + (size_t)node * CAP;
    for (int base = 0; base < deg; base += 32) {
        int n = deg - base;
        if (n > 32) n = 32;
        int cidx = (lane < n) ? adj[base + lane] : 0;
        int j = 0;
        for (; j + 3 < n; j += 4) {
            int c0 = __shfl_sync(0xffffffffu, cidx, j);
            int c1 = __shfl_sync(0xffffffffu, cidx, j + 1);
            int c2 = __shfl_sync(0xffffffffu, cidx, j + 2);
            int c3 = __shfl_sync(0xffffffffu, cidx, j + 3);
            uint2 u0 = ((const uint2*)(g_hw + (size_t)c0 * HH))[lane];
            uint2 u1 = ((const uint2*)(g_hw + (size_t)c1 * HH))[lane];
            uint2 u2 = ((const uint2*)(g_hw + (size_t)c2 * HH))[lane];
            uint2 u3 = ((const uint2*)(g_hw + (size_t)c3 * HH))[lane];
            add_half4(acc, u0);
            add_half4(acc, u1);
            add_half4(acc, u2);
            add_half4(acc, u3);
        }
        for (; j < n; j++) {
            int c = __shfl_sync(0xffffffffu, cidx, j);
            add_half4(acc, ((const uint2*)(g_hw + (size_t)c * HH))[lane]);
        }
    }

    float dr = rsqrtf(1.0f + (float)deg);
    float4 A = ((const float4*)(g_bnA + layer * HH))[lane];
    float4 B = ((const float4*)(g_bnB + layer * HH))[lane];
    __half2 p0 = __floats2half2_rn(fmaxf(fmaf(acc.x * dr, A.x, B.x), 0.f),
                                   fmaxf(fmaf(acc.y * dr, A.y, B.y), 0.f));
    __half2 p1 = __floats2half2_rn(fmaxf(fmaf(acc.z * dr, A.z, B.z), 0.f),
                                   fmaxf(fmaf(acc.w * dr, A.w, B.w), 0.f));
    uint2 o = make_uint2(*(uint32_t*)&p0, *(uint32_t*)&p1);
    ((uint2*)(g_h + (size_t)node * HH))[lane] = o;
}

// ---------------- pooling (batch sorted: register segments, flush on boundary) ----------------
__global__ void k_pool(const int* __restrict__ batch) {
    int f = threadIdx.x;
    int n0 = blockIdx.x * 32;
    int curg = batch[n0];
    float s = 0.f, m = 0.f;
    int c = 0;
    for (int i = 0; i < 32; i++) {
        int n = n0 + i;
        if (n >= NN) break;
        int g = batch[n];
        if (g != curg) {
            atomicAdd(&g_psum[curg * HH + f], s);
            atomicMax((int*)&g_pmax[curg * HH + f], __float_as_int(m));
            if (f == 0) atomicAdd(&g_cnt[curg], c);
            s = 0.f; m = 0.f; c = 0; curg = g;
        }
        float v = __half2float(g_h[(size_t)n * HH + f]);
        s += v;
        m = fmaxf(m, v);
        c++;
    }
    atomicAdd(&g_psum[curg * HH + f], s);
    atomicMax((int*)&g_pmax[curg * HH + f], __float_as_int(m));
    if (f == 0) atomicAdd(&g_cnt[curg], c);
}

// ---------------- final MLP ----------------
__global__ void k_mlp(const float* __restrict__ W1, const float* __restrict__ b1,
                      const float* __restrict__ W2, const float* __restrict__ b2,
                      float* __restrict__ out) {
    __shared__ float gv[2 * HH];
    __shared__ float hid[HH];
    int g = blockIdx.x, t = threadIdx.x;  // 128
    float cntf = fmaxf((float)g_cnt[g], 1.0f);
    gv[t] = g_psum[g * HH + t] / cntf;
    gv[HH + t] = g_pmax[g * HH + t];
    __syncthreads();
    float acc = b1[t];
#pragma unroll 8
    for (int k = 0; k < 2 * HH; k++)
        acc = fmaf(gv[k], W1[k * HH + t], acc);
    hid[t] = fmaxf(acc, 0.0f);
    __syncthreads();
    if (t < CC) {
        float o = b2[t];
#pragma unroll 8
        for (int c = 0; c < HH; c++)
            o = fmaf(hid[c], W2[c * CC + t], o);
        out[g * CC + t] = o;
    }
}

// ---------------- persistent side streams/events (created once; no device mem) ----------------
static cudaStream_t make_stream() {
    cudaStream_t s;
    cudaStreamCreateWithFlags(&s, cudaStreamNonBlocking);
    return s;
}
static cudaEvent_t make_event() {
    cudaEvent_t e;
    cudaEventCreateWithFlags(&e, cudaEventDisableTiming);
    return e;
}

// ---------------- launch ----------------
extern "C" void kernel_launch(void* const* d_in, const int* in_sizes, int n_in,
                              void* d_out, int out_size) {
    const float* x     = (const float*)d_in[0];
    const int*   ei    = (const int*)d_in[1];
    const int*   batch = (const int*)d_in[2];
    const float* Wp    = (const float*)d_in[3];
    const float* bp    = (const float*)d_in[4];
    const float* Wc    = (const float*)d_in[5];
    const float* bc    = (const float*)d_in[6];
    const float* bn_g  = (const float*)d_in[7];
    const float* bn_b  = (const float*)d_in[8];
    const float* bn_m  = (const float*)d_in[9];
    const float* bn_v  = (const float*)d_in[10];
    const float* W1    = (const float*)d_in[11];
    const float* b1    = (const float*)d_in[12];
    const float* W2    = (const float*)d_in[13];
    const float* b2    = (const float*)d_in[14];
    float* out = (float*)d_out;

    const int4* rows4 = (const int4*)ei;
    const int4* cols4 = (const int4*)(ei + EE);

    static cudaStream_t s1 = make_stream();
    static cudaEvent_t ev_fork = make_event();
    static cudaEvent_t ev_j1 = make_event();

    const int gemm_smem = 65536;
    cudaFuncSetAttribute(k_gemm_hmma, cudaFuncAttributeMaxDynamicSharedMemorySize, gemm_smem);

    // fork: prep + proj (side stream) run concurrently with adjacency build (stream 0)
    cudaEventRecord(ev_fork, 0);
    cudaStreamWaitEvent(s1, ev_fork, 0);

    k_prep<<<LL * 32, 256, 0, s1>>>(Wc, bc, bn_g, bn_b, bn_m, bn_v);
    k_proj<<<(NN + 63) / 64, 128, 0, s1>>>(x, Wp, bp);

    k_init<<<(NN + 255) / 256, 256>>>();
    k_fill<<<(EE / 4 + 255) / 256, 256>>>(rows4, cols4);

    // join
    cudaEventRecord(ev_j1, s1);
    cudaStreamWaitEvent(0, ev_j1, 0);

    for (int l = 0; l < LL; l++) {
        k_gemm_hmma<<<(NN + 127) / 128, 512, gemm_smem>>>(l);
        k_gather_bn<<<(NN + 3) / 4, 128>>>(l);
    }

    k_pool<<<NN / 32, 128>>>(batch);
    k_mlp<<<GG, 128>>>(W1, b1, W2, b2, out);
}